// round 6
// baseline (speedup 1.0000x reference)
#include <cuda_runtime.h>
#include <math.h>

// ---------------- scratch (no allocs allowed) ----------------
#define MAX_T (64 * 4096)
#define MAX_B 64
#define MAX_K 1024
__device__ float g_dot[MAX_T];          // per-node dot(logits, proj)
__device__ int   g_idx[MAX_B * MAX_K];  // selected global node indices per graph

// ---------------- kernel 1: per-row dot product ----------------
// One warp per 4 rows; all 8 float4 loads issued before reduction (MLP=8).
__global__ void dot_kernel(const float* __restrict__ logits,
                           const float* __restrict__ proj,
                           float* __restrict__ dots,
                           int rowBase, int rowEnd) {
    __shared__ float4 pS[64];
    int tid = threadIdx.x;
    if (tid < 64) pS[tid] = reinterpret_cast<const float4*>(proj)[tid];
    __syncthreads();

    int warp = tid >> 5, lane = tid & 31;
    int row0 = rowBase + (blockIdx.x * 8 + warp) * 4;
    if (row0 >= rowEnd) return;

    const float4* rp = reinterpret_cast<const float4*>(logits) + (size_t)row0 * 64;

    float4 a[4], c[4];
#pragma unroll
    for (int r = 0; r < 4; r++) {
        a[r] = rp[(size_t)r * 64 + lane];
        c[r] = rp[(size_t)r * 64 + lane + 32];
    }
    float4 pa = pS[lane];
    float4 pc = pS[lane + 32];

    float s[4];
#pragma unroll
    for (int r = 0; r < 4; r++) {
        s[r] = a[r].x * pa.x + a[r].y * pa.y + a[r].z * pa.z + a[r].w * pa.w
             + c[r].x * pc.x + c[r].y * pc.y + c[r].z * pc.z + c[r].w * pc.w;
#pragma unroll
        for (int o = 16; o; o >>= 1) s[r] += __shfl_xor_sync(0xFFFFFFFFu, s[r], o);
    }
    if (lane < 4) dots[row0 + lane] = s[lane];
}

// ---------------- kernel 2: per-graph radix select + compaction ----------------
// One block (512 threads) per graph. 4x 8-bit MSB-first radix passes; bin
// choice via two-level warp suffix-scan. Also zeroes this graph's output row.
__global__ void __launch_bounds__(512)
select_kernel(const float* __restrict__ dots,
              int* __restrict__ idxList,
              float* __restrict__ out,
              int N, int K, int D, int bBase) {
    __shared__ unsigned keys[4096];
    __shared__ unsigned hist[256];
    __shared__ unsigned warpTot[8];
    __shared__ unsigned s_chosen;
    __shared__ unsigned s_need;
    __shared__ int cntGT, cntEQ;

    int b = bBase + blockIdx.x, tid = threadIdx.x;
    int lane = tid & 31, warp = tid >> 5;
    const float* d = dots + (size_t)b * N;

    for (int i = tid; i < D; i += blockDim.x) out[(size_t)b * D + i] = 0.0f;

    for (int i = tid; i < N; i += blockDim.x) {
        unsigned u = __float_as_uint(d[i]);
        u ^= (u >> 31) ? 0xFFFFFFFFu : 0x80000000u;  // order-preserving
        keys[i] = u;
    }
    if (tid == 0) s_need = (unsigned)K;
    __syncthreads();

    unsigned prefix = 0, mask = 0;
#pragma unroll
    for (int pass = 0; pass < 4; pass++) {
        int shift = 24 - 8 * pass;
        unsigned need = s_need;
        if (tid < 256) hist[tid] = 0;
        __syncthreads();
        for (int i = tid; i < N; i += blockDim.x) {
            unsigned kk = keys[i];
            if ((kk & mask) == prefix)
                atomicAdd(&hist[(kk >> shift) & 0xFFu], 1u);
        }
        __syncthreads();
        // two-level suffix scan over 256 bins
        if (warp < 8) {
            unsigned sum = hist[warp * 32 + lane];
#pragma unroll
            for (int o = 1; o < 32; o <<= 1) {
                unsigned t = __shfl_down_sync(0xFFFFFFFFu, sum, o);
                if (lane + o < 32) sum += t;
            }
            if (lane == 0) warpTot[warp] = sum;
            __syncwarp();
            hist[warp * 32 + lane] = sum;   // intra-warp inclusive suffix
        }
        __syncthreads();
        if (tid < 256) {
            unsigned add = 0;
            int myw = tid >> 5;
#pragma unroll
            for (int w = 0; w < 8; w++)
                if (w > myw) add += warpTot[w];
            unsigned st = hist[tid] + add;
            unsigned sn;
            if (tid == 255) sn = 0;
            else if ((tid & 31) == 31) sn = add;
            else sn = hist[tid + 1] + add;
            if (st >= need && sn < need) {
                s_chosen = (unsigned)tid;
                s_need = need - sn;
            }
        }
        __syncthreads();
        prefix |= s_chosen << shift;
        mask   |= 0xFFu << shift;
        __syncthreads();
    }

    unsigned thr = prefix;  // exact key of the k-th largest
    if (tid == 0) {
        cntGT = 0;
        cntEQ = K - (int)s_need;  // ties fill [G, K)
    }
    __syncthreads();

    int* lst = idxList + (size_t)b * K;
    for (int i = tid; i < N; i += blockDim.x) {
        unsigned kk = keys[i];
        if (kk > thr) {
            int p = atomicAdd(&cntGT, 1);
            lst[p] = b * N + i;
        } else if (kk == thr) {
            int p = atomicAdd(&cntEQ, 1);
            if (p < K) lst[p] = b * N + i;
        }
    }
}

// ---------------- kernel 3: gather + segment sum (float4, high-MLP) ----------------
// 256 threads = 4 row-groups x 64 lanes. Group g handles rows g, g+4, ...
// Each thread loads one float4 per row; 4 rows in flight per iteration
// (64B/thread outstanding). smem reduce across the 4 groups, then one
// atomicAdd per output float.
__global__ void __launch_bounds__(256)
gather_sum_kernel(const float* __restrict__ logits,
                  const int* __restrict__ idxList,
                  float* __restrict__ out,
                  int K, int D, int SPLIT, int bBase) {
    __shared__ int sidx[64];
    __shared__ float4 part[4][64];

    int b = bBase + blockIdx.x / SPLIT;
    int s = blockIdx.x % SPLIT;
    int tid = threadIdx.x;
    int grp = tid >> 6;        // 0..3
    int l64 = tid & 63;        // float4 column within row

    int per = (K + SPLIT - 1) / SPLIT;
    int r0 = s * per;
    int cnt = min(K, r0 + per) - r0;   // uniform across block

    if (tid < cnt) sidx[tid] = idxList[(size_t)b * K + r0 + tid];
    __syncthreads();

    float4 acc = make_float4(0.f, 0.f, 0.f, 0.f);
    int nD4 = D >> 2;  // 64
    if (cnt > 0) {
        int r = grp;
        // 4 rows (stride 4) in flight per iteration
        for (; r + 12 < cnt; r += 16) {
            const float4* p0 = reinterpret_cast<const float4*>(logits) + (size_t)sidx[r +  0] * nD4;
            const float4* p1 = reinterpret_cast<const float4*>(logits) + (size_t)sidx[r +  4] * nD4;
            const float4* p2 = reinterpret_cast<const float4*>(logits) + (size_t)sidx[r +  8] * nD4;
            const float4* p3 = reinterpret_cast<const float4*>(logits) + (size_t)sidx[r + 12] * nD4;
            float4 v0 = p0[l64], v1 = p1[l64], v2 = p2[l64], v3 = p3[l64];
            acc.x += (v0.x + v1.x) + (v2.x + v3.x);
            acc.y += (v0.y + v1.y) + (v2.y + v3.y);
            acc.z += (v0.z + v1.z) + (v2.z + v3.z);
            acc.w += (v0.w + v1.w) + (v2.w + v3.w);
        }
        for (; r < cnt; r += 4) {
            const float4* p = reinterpret_cast<const float4*>(logits) + (size_t)sidx[r] * nD4;
            float4 v = p[l64];
            acc.x += v.x; acc.y += v.y; acc.z += v.z; acc.w += v.w;
        }
    }
    part[grp][l64] = acc;
    __syncthreads();

    if (cnt > 0) {
        // thread tid owns output float tid: float4 col = tid>>2, comp = tid&3
        int col = tid >> 2, comp = tid & 3;
        const float* q0 = reinterpret_cast<const float*>(&part[0][col]);
        const float* q1 = reinterpret_cast<const float*>(&part[1][col]);
        const float* q2 = reinterpret_cast<const float*>(&part[2][col]);
        const float* q3 = reinterpret_cast<const float*>(&part[3][col]);
        float v = (q0[comp] + q1[comp]) + (q2[comp] + q3[comp]);
        atomicAdd(&out[(size_t)b * D + tid], v);
    }
}

// ---------------- launcher: 3-chunk asymmetric pipelined DAG ----------------
extern "C" void kernel_launch(void* const* d_in, const int* in_sizes, int n_in,
                              void* d_out, int out_size) {
    const float* logits = (const float*)d_in[0];
    const float* proj = (const float*)d_in[2];
    float* out = (float*)d_out;

    int D = in_sizes[2];                 // 256
    int T = in_sizes[1];                 // 262144
    int B = out_size / D;                // 64
    int N = T / B;                       // 4096
    int K = (int)ceil(0.2 * (double)N);  // 820

    float* dots;
    int* idxList;
    cudaGetSymbolAddress((void**)&dots, g_dot);
    cudaGetSymbolAddress((void**)&idxList, g_idx);

    // Lazily created side stream/events (first call is the eager correctness
    // call, so creation never happens during graph capture).
    static cudaStream_t sSide = nullptr;
    static cudaEvent_t evDot[3], evSideDone;
    if (sSide == nullptr) {
        cudaStreamCreateWithFlags(&sSide, cudaStreamNonBlocking);
        for (int i = 0; i < 3; i++)
            cudaEventCreateWithFlags(&evDot[i], cudaEventDisableTiming);
        cudaEventCreateWithFlags(&evSideDone, cudaEventDisableTiming);
    }

    // asymmetric chunk sizes (graphs): shrink toward the end to minimize tail
    int g0 = B / 2;                     // 32
    int g1 = (B - g0) * 2 / 3;          // 21
    int g2 = B - g0 - g1;               // 11
    int sizes[3] = {g0, g1, g2};
    int bases[3] = {0, g0, g0 + g1};
    const int SPLIT = 32;

    // main stream: three dot chunks back-to-back, event after each
    for (int c = 0; c < 3; c++) {
        if (sizes[c] <= 0) { cudaEventRecord(evDot[c], 0); continue; }
        int rb = bases[c] * N, re = rb + sizes[c] * N;
        dot_kernel<<<(sizes[c] * N + 31) / 32, 256>>>(logits, proj, dots, rb, re);
        cudaEventRecord(evDot[c], 0);
    }

    // side stream: select + gather per chunk, each gated by its dot event
    for (int c = 0; c < 3; c++) {
        if (sizes[c] <= 0) continue;
        cudaStreamWaitEvent(sSide, evDot[c], 0);
        select_kernel<<<sizes[c], 512, 0, sSide>>>(dots, idxList, out,
                                                   N, K, D, bases[c]);
        gather_sum_kernel<<<sizes[c] * SPLIT, 256, 0, sSide>>>(logits, idxList, out,
                                                               K, D, SPLIT, bases[c]);
    }
    cudaEventRecord(evSideDone, sSide);

    // join side stream back into the main stream
    cudaStreamWaitEvent(0, evSideDone, 0);
}

// round 7
// speedup vs baseline: 1.1676x; 1.1676x over previous
#include <cuda_runtime.h>
#include <math.h>

// ---------------- scratch (no allocs allowed) ----------------
#define MAX_T (64 * 4096)
#define MAX_B 64
#define MAX_K 1024
__device__ float g_dot[MAX_T];          // per-node dot(logits, proj)
__device__ int   g_idx[MAX_B * MAX_K];  // selected global node indices per graph

// ---------------- kernel 1: per-row dot product ----------------
__global__ void dot_kernel(const float* __restrict__ logits,
                           const float* __restrict__ proj,
                           float* __restrict__ dots,
                           int rowBase, int rowEnd) {
    __shared__ float4 pS[64];
    int tid = threadIdx.x;
    if (tid < 64) pS[tid] = reinterpret_cast<const float4*>(proj)[tid];
    __syncthreads();

    int warp = tid >> 5, lane = tid & 31;
    int row0 = rowBase + (blockIdx.x * 8 + warp) * 4;
    if (row0 >= rowEnd) return;

    const float4* rp = reinterpret_cast<const float4*>(logits) + (size_t)row0 * 64;

    float4 a[4], c[4];
#pragma unroll
    for (int r = 0; r < 4; r++) {
        a[r] = rp[(size_t)r * 64 + lane];
        c[r] = rp[(size_t)r * 64 + lane + 32];
    }
    float4 pa = pS[lane];
    float4 pc = pS[lane + 32];

    float s[4];
#pragma unroll
    for (int r = 0; r < 4; r++) {
        s[r] = a[r].x * pa.x + a[r].y * pa.y + a[r].z * pa.z + a[r].w * pa.w
             + c[r].x * pc.x + c[r].y * pc.y + c[r].z * pc.z + c[r].w * pc.w;
#pragma unroll
        for (int o = 16; o; o >>= 1) s[r] += __shfl_xor_sync(0xFFFFFFFFu, s[r], o);
    }
    if (lane < 4) dots[row0 + lane] = s[lane];
}

// ---------------- kernel 2: per-graph radix select (warp-aggregated) ----------------
// One block (512 threads) per graph. 4x 8-bit MSB-first radix passes.
// Histogram uses __match_any_sync aggregation (keys cluster in few exponent
// bins -> raw smem atomics serialize badly). Compaction uses ballot-aggregated
// shared counters. Also zeroes this graph's output row.
__global__ void __launch_bounds__(512)
select_kernel(const float* __restrict__ dots,
              int* __restrict__ idxList,
              float* __restrict__ out,
              int N, int K, int D, int bBase) {
    __shared__ unsigned keys[4096];
    __shared__ unsigned hist[256];
    __shared__ unsigned warpTot[8];
    __shared__ unsigned s_chosen;
    __shared__ unsigned s_need;
    __shared__ int cntGT, cntEQ;

    int b = bBase + blockIdx.x, tid = threadIdx.x;
    int lane = tid & 31, warp = tid >> 5;
    const float* d = dots + (size_t)b * N;

    for (int i = tid; i < D; i += blockDim.x) out[(size_t)b * D + i] = 0.0f;

    for (int i = tid; i < N; i += blockDim.x) {
        unsigned u = __float_as_uint(d[i]);
        u ^= (u >> 31) ? 0xFFFFFFFFu : 0x80000000u;  // order-preserving
        keys[i] = u;
    }
    if (tid == 0) s_need = (unsigned)K;
    __syncthreads();

    unsigned prefix = 0, mask = 0;
#pragma unroll
    for (int pass = 0; pass < 4; pass++) {
        int shift = 24 - 8 * pass;
        unsigned need = s_need;
        if (tid < 256) hist[tid] = 0;
        __syncthreads();
        for (int i = tid; i < N; i += blockDim.x) {
            unsigned kk = keys[i];
            bool pred = ((kk & mask) == prefix);
            unsigned bin = (kk >> shift) & 0xFFu;
            unsigned act = __ballot_sync(0xFFFFFFFFu, pred);
            if (pred) {
                unsigned mm = __match_any_sync(act, bin);
                int leader = __ffs(mm) - 1;
                if (lane == leader) atomicAdd(&hist[bin], (unsigned)__popc(mm));
            }
        }
        __syncthreads();
        // two-level suffix scan over 256 bins
        if (warp < 8) {
            unsigned sum = hist[warp * 32 + lane];
#pragma unroll
            for (int o = 1; o < 32; o <<= 1) {
                unsigned t = __shfl_down_sync(0xFFFFFFFFu, sum, o);
                if (lane + o < 32) sum += t;
            }
            if (lane == 0) warpTot[warp] = sum;
            __syncwarp();
            hist[warp * 32 + lane] = sum;   // intra-warp inclusive suffix
        }
        __syncthreads();
        if (tid < 256) {
            unsigned add = 0;
            int myw = tid >> 5;
#pragma unroll
            for (int w = 0; w < 8; w++)
                if (w > myw) add += warpTot[w];
            unsigned st = hist[tid] + add;
            unsigned sn;
            if (tid == 255) sn = 0;
            else if ((tid & 31) == 31) sn = add;
            else sn = hist[tid + 1] + add;
            if (st >= need && sn < need) {
                s_chosen = (unsigned)tid;
                s_need = need - sn;
            }
        }
        __syncthreads();
        prefix |= s_chosen << shift;
        mask   |= 0xFFu << shift;
        __syncthreads();
    }

    unsigned thr = prefix;  // exact key of the k-th largest
    if (tid == 0) {
        cntGT = 0;
        cntEQ = K - (int)s_need;  // ties fill [G, K)
    }
    __syncthreads();

    int* lst = idxList + (size_t)b * K;
    unsigned lmLT = (1u << lane) - 1u;
    for (int i = tid; i < N; i += blockDim.x) {
        unsigned kk = keys[i];
        bool isGT = (kk > thr), isEQ = (kk == thr);
        // warp-aggregated compaction for the GT stream
        unsigned bGT = __ballot_sync(0xFFFFFFFFu, isGT);
        if (bGT) {
            int base = 0;
            int leader = __ffs(bGT) - 1;
            if (lane == leader) base = atomicAdd(&cntGT, __popc(bGT));
            base = __shfl_sync(0xFFFFFFFFu, base, leader);
            if (isGT) lst[base + __popc(bGT & lmLT)] = b * N + i;
        }
        // EQ stream (rare): aggregated too, bounded by K
        unsigned bEQ = __ballot_sync(0xFFFFFFFFu, isEQ);
        if (bEQ) {
            int base = 0;
            int leader = __ffs(bEQ) - 1;
            if (lane == leader) base = atomicAdd(&cntEQ, __popc(bEQ));
            base = __shfl_sync(0xFFFFFFFFu, base, leader);
            if (isEQ) {
                int p = base + __popc(bEQ & lmLT);
                if (p < K) lst[p] = b * N + i;
            }
        }
    }
}

// ---------------- kernel 3: gather + segment sum (float4, high-MLP) ----------------
__global__ void __launch_bounds__(256)
gather_sum_kernel(const float* __restrict__ logits,
                  const int* __restrict__ idxList,
                  float* __restrict__ out,
                  int K, int D, int SPLIT, int bBase) {
    __shared__ int sidx[64];
    __shared__ float4 part[4][64];

    int b = bBase + blockIdx.x / SPLIT;
    int s = blockIdx.x % SPLIT;
    int tid = threadIdx.x;
    int grp = tid >> 6;        // 0..3
    int l64 = tid & 63;        // float4 column within row

    int per = (K + SPLIT - 1) / SPLIT;
    int r0 = s * per;
    int cnt = min(K, r0 + per) - r0;   // uniform across block

    if (tid < cnt) sidx[tid] = idxList[(size_t)b * K + r0 + tid];
    __syncthreads();

    float4 acc = make_float4(0.f, 0.f, 0.f, 0.f);
    int nD4 = D >> 2;  // 64
    if (cnt > 0) {
        int r = grp;
        for (; r + 12 < cnt; r += 16) {
            const float4* p0 = reinterpret_cast<const float4*>(logits) + (size_t)sidx[r +  0] * nD4;
            const float4* p1 = reinterpret_cast<const float4*>(logits) + (size_t)sidx[r +  4] * nD4;
            const float4* p2 = reinterpret_cast<const float4*>(logits) + (size_t)sidx[r +  8] * nD4;
            const float4* p3 = reinterpret_cast<const float4*>(logits) + (size_t)sidx[r + 12] * nD4;
            float4 v0 = p0[l64], v1 = p1[l64], v2 = p2[l64], v3 = p3[l64];
            acc.x += (v0.x + v1.x) + (v2.x + v3.x);
            acc.y += (v0.y + v1.y) + (v2.y + v3.y);
            acc.z += (v0.z + v1.z) + (v2.z + v3.z);
            acc.w += (v0.w + v1.w) + (v2.w + v3.w);
        }
        for (; r < cnt; r += 4) {
            const float4* p = reinterpret_cast<const float4*>(logits) + (size_t)sidx[r] * nD4;
            float4 v = p[l64];
            acc.x += v.x; acc.y += v.y; acc.z += v.z; acc.w += v.w;
        }
    }
    part[grp][l64] = acc;
    __syncthreads();

    if (cnt > 0) {
        int col = tid >> 2, comp = tid & 3;
        const float* q0 = reinterpret_cast<const float*>(&part[0][col]);
        const float* q1 = reinterpret_cast<const float*>(&part[1][col]);
        const float* q2 = reinterpret_cast<const float*>(&part[2][col]);
        const float* q3 = reinterpret_cast<const float*>(&part[3][col]);
        float v = (q0[comp] + q1[comp]) + (q2[comp] + q3[comp]);
        atomicAdd(&out[(size_t)b * D + tid], v);
    }
}

// ---------------- launcher: 2-chunk asymmetric pipelined DAG ----------------
extern "C" void kernel_launch(void* const* d_in, const int* in_sizes, int n_in,
                              void* d_out, int out_size) {
    const float* logits = (const float*)d_in[0];
    const float* proj = (const float*)d_in[2];
    float* out = (float*)d_out;

    int D = in_sizes[2];                 // 256
    int T = in_sizes[1];                 // 262144
    int B = out_size / D;                // 64
    int N = T / B;                       // 4096
    int K = (int)ceil(0.2 * (double)N);  // 820

    float* dots;
    int* idxList;
    cudaGetSymbolAddress((void**)&dots, g_dot);
    cudaGetSymbolAddress((void**)&idxList, g_idx);

    static cudaStream_t sSide = nullptr;
    static cudaEvent_t evDot0, evSideDone;
    if (sSide == nullptr) {
        cudaStreamCreateWithFlags(&sSide, cudaStreamNonBlocking);
        cudaEventCreateWithFlags(&evDot0, cudaEventDisableTiming);
        cudaEventCreateWithFlags(&evSideDone, cudaEventDisableTiming);
    }

    // asymmetric 2-chunk split: bigger first chunk -> smaller exposed tail
    int g0 = (B >= 2) ? (B * 9 / 16) : B;   // 36 for B=64
    int g1 = B - g0;                         // 28
    const int SPLIT = 32;

    // chunk 0 dots on main stream
    dot_kernel<<<(g0 * N + 31) / 32, 256>>>(logits, proj, dots, 0, g0 * N);
    cudaEventRecord(evDot0, 0);

    // chunk 1 dots on main stream (overlaps side select/gather of chunk 0)
    if (g1 > 0) {
        dot_kernel<<<(g1 * N + 31) / 32, 256>>>(logits, proj, dots,
                                                g0 * N, (g0 + g1) * N);
    }

    // side stream: select + gather for chunk 0
    cudaStreamWaitEvent(sSide, evDot0, 0);
    select_kernel<<<g0, 512, 0, sSide>>>(dots, idxList, out, N, K, D, 0);
    gather_sum_kernel<<<g0 * SPLIT, 256, 0, sSide>>>(logits, idxList, out,
                                                     K, D, SPLIT, 0);
    cudaEventRecord(evSideDone, sSide);

    // main stream tail: select + gather for chunk 1
    if (g1 > 0) {
        select_kernel<<<g1, 512>>>(dots, idxList, out, N, K, D, g0);
        gather_sum_kernel<<<g1 * SPLIT, 256>>>(logits, idxList, out,
                                               K, D, SPLIT, g0);
    }

    // join side stream back into the main stream
    cudaStreamWaitEvent(0, evSideDone, 0);
}

// round 8
// speedup vs baseline: 1.3522x; 1.1581x over previous
#include <cuda_runtime.h>
#include <math.h>

// ---------------- scratch (no allocs allowed) ----------------
#define MAX_T (64 * 4096)
#define MAX_B 64
#define MAX_K 1024
__device__ float g_dot[MAX_T];          // per-node dot(logits, proj)
__device__ int   g_idx[MAX_B * MAX_K];  // selected global node indices per graph

// ---------------- kernel 1: per-row dot product ----------------
// One warp per 4 rows; all 8 float4 loads issued before reduction (MLP=8).
__global__ void dot_kernel(const float* __restrict__ logits,
                           const float* __restrict__ proj,
                           float* __restrict__ dots,
                           int rowBase, int rowEnd) {
    __shared__ float4 pS[64];
    int tid = threadIdx.x;
    if (tid < 64) pS[tid] = reinterpret_cast<const float4*>(proj)[tid];
    __syncthreads();

    int warp = tid >> 5, lane = tid & 31;
    int row0 = rowBase + (blockIdx.x * 8 + warp) * 4;
    if (row0 >= rowEnd) return;

    const float4* rp = reinterpret_cast<const float4*>(logits) + (size_t)row0 * 64;

    float4 a[4], c[4];
#pragma unroll
    for (int r = 0; r < 4; r++) {
        a[r] = rp[(size_t)r * 64 + lane];
        c[r] = rp[(size_t)r * 64 + lane + 32];
    }
    float4 pa = pS[lane];
    float4 pc = pS[lane + 32];

    float s[4];
#pragma unroll
    for (int r = 0; r < 4; r++) {
        s[r] = a[r].x * pa.x + a[r].y * pa.y + a[r].z * pa.z + a[r].w * pa.w
             + c[r].x * pc.x + c[r].y * pc.y + c[r].z * pc.z + c[r].w * pc.w;
#pragma unroll
        for (int o = 16; o; o >>= 1) s[r] += __shfl_xor_sync(0xFFFFFFFFu, s[r], o);
    }
    if (lane < 4) dots[row0 + lane] = s[lane];
}

// ---------------- kernel 2: per-graph radix select (warp-aggregated) ----------------
// One block (512 threads) per graph. 4x 8-bit MSB-first radix passes.
// Histogram via __match_any_sync aggregation (Gaussian keys cluster in ~14
// exponent bins -> raw smem atomics serialize). Ballot-aggregated compaction.
// Also zeroes this graph's output row.
__global__ void __launch_bounds__(512)
select_kernel(const float* __restrict__ dots,
              int* __restrict__ idxList,
              float* __restrict__ out,
              int N, int K, int D, int bBase) {
    __shared__ unsigned keys[4096];
    __shared__ unsigned hist[256];
    __shared__ unsigned warpTot[8];
    __shared__ unsigned s_chosen;
    __shared__ unsigned s_need;
    __shared__ int cntGT, cntEQ;

    int b = bBase + blockIdx.x, tid = threadIdx.x;
    int lane = tid & 31, warp = tid >> 5;
    const float* d = dots + (size_t)b * N;

    for (int i = tid; i < D; i += blockDim.x) out[(size_t)b * D + i] = 0.0f;

    for (int i = tid; i < N; i += blockDim.x) {
        unsigned u = __float_as_uint(d[i]);
        u ^= (u >> 31) ? 0xFFFFFFFFu : 0x80000000u;  // order-preserving
        keys[i] = u;
    }
    if (tid == 0) s_need = (unsigned)K;
    __syncthreads();

    unsigned prefix = 0, mask = 0;
#pragma unroll
    for (int pass = 0; pass < 4; pass++) {
        int shift = 24 - 8 * pass;
        unsigned need = s_need;
        if (tid < 256) hist[tid] = 0;
        __syncthreads();
        for (int i = tid; i < N; i += blockDim.x) {
            unsigned kk = keys[i];
            bool pred = ((kk & mask) == prefix);
            unsigned bin = (kk >> shift) & 0xFFu;
            unsigned act = __ballot_sync(0xFFFFFFFFu, pred);
            if (pred) {
                unsigned mm = __match_any_sync(act, bin);
                int leader = __ffs(mm) - 1;
                if (lane == leader) atomicAdd(&hist[bin], (unsigned)__popc(mm));
            }
        }
        __syncthreads();
        // two-level suffix scan over 256 bins
        if (warp < 8) {
            unsigned sum = hist[warp * 32 + lane];
#pragma unroll
            for (int o = 1; o < 32; o <<= 1) {
                unsigned t = __shfl_down_sync(0xFFFFFFFFu, sum, o);
                if (lane + o < 32) sum += t;
            }
            if (lane == 0) warpTot[warp] = sum;
            __syncwarp();
            hist[warp * 32 + lane] = sum;   // intra-warp inclusive suffix
        }
        __syncthreads();
        if (tid < 256) {
            unsigned add = 0;
            int myw = tid >> 5;
#pragma unroll
            for (int w = 0; w < 8; w++)
                if (w > myw) add += warpTot[w];
            unsigned st = hist[tid] + add;
            unsigned sn;
            if (tid == 255) sn = 0;
            else if ((tid & 31) == 31) sn = add;
            else sn = hist[tid + 1] + add;
            if (st >= need && sn < need) {
                s_chosen = (unsigned)tid;
                s_need = need - sn;
            }
        }
        __syncthreads();
        prefix |= s_chosen << shift;
        mask   |= 0xFFu << shift;
        __syncthreads();
    }

    unsigned thr = prefix;  // exact key of the k-th largest
    if (tid == 0) {
        cntGT = 0;
        cntEQ = K - (int)s_need;  // ties fill [G, K)
    }
    __syncthreads();

    int* lst = idxList + (size_t)b * K;
    unsigned lmLT = (1u << lane) - 1u;
    for (int i = tid; i < N; i += blockDim.x) {
        unsigned kk = keys[i];
        bool isGT = (kk > thr), isEQ = (kk == thr);
        unsigned bGT = __ballot_sync(0xFFFFFFFFu, isGT);
        if (bGT) {
            int base = 0;
            int leader = __ffs(bGT) - 1;
            if (lane == leader) base = atomicAdd(&cntGT, __popc(bGT));
            base = __shfl_sync(0xFFFFFFFFu, base, leader);
            if (isGT) lst[base + __popc(bGT & lmLT)] = b * N + i;
        }
        unsigned bEQ = __ballot_sync(0xFFFFFFFFu, isEQ);
        if (bEQ) {
            int base = 0;
            int leader = __ffs(bEQ) - 1;
            if (lane == leader) base = atomicAdd(&cntEQ, __popc(bEQ));
            base = __shfl_sync(0xFFFFFFFFu, base, leader);
            if (isEQ) {
                int p = base + __popc(bEQ & lmLT);
                if (p < K) lst[p] = b * N + i;
            }
        }
    }
}

// ---------------- kernel 3: gather + segment sum (single load-wave) ----------------
// 256 threads = 4 row-groups x 64 lanes. Group g owns rows g, g+4, ... (<=7
// rows at SPLIT=32). ALL of a group's loads are issued as one predicated
// unrolled wave (<=7 float4 = 112B in flight per thread, no serial tail),
// then accumulated. smem reduce across groups, one atomicAdd per out float.
#define GSPLIT 32
__global__ void __launch_bounds__(256)
gather_sum_kernel(const float* __restrict__ logits,
                  const int* __restrict__ idxList,
                  float* __restrict__ out,
                  int K, int D, int bBase) {
    __shared__ int sidx[32];
    __shared__ float4 part[4][64];

    int b = bBase + blockIdx.x / GSPLIT;
    int s = blockIdx.x % GSPLIT;
    int tid = threadIdx.x;
    int grp = tid >> 6;        // 0..3
    int l64 = tid & 63;        // float4 column within row

    int per = (K + GSPLIT - 1) / GSPLIT;          // 26 for K=820
    int r0 = s * per;
    int cnt = min(K, r0 + per) - r0;              // <= 26

    if (tid < cnt) sidx[tid] = idxList[(size_t)b * K + r0 + tid];
    __syncthreads();

    const float4* lg4 = reinterpret_cast<const float4*>(logits);
    int nD4 = D >> 2;  // 64

    // one predicated load wave: rows grp, grp+4, ..., up to 7 slots
    float4 v[7];
#pragma unroll
    for (int j = 0; j < 7; j++) {
        int r = grp + 4 * j;
        if (r < cnt) v[j] = lg4[(size_t)sidx[r] * nD4 + l64];
    }

    float4 acc = make_float4(0.f, 0.f, 0.f, 0.f);
#pragma unroll
    for (int j = 0; j < 7; j++) {
        int r = grp + 4 * j;
        if (r < cnt) {
            acc.x += v[j].x; acc.y += v[j].y;
            acc.z += v[j].z; acc.w += v[j].w;
        }
    }
    part[grp][l64] = acc;
    __syncthreads();

    if (cnt > 0) {
        // thread tid owns output float tid: float4 col = tid>>2, comp = tid&3
        int col = tid >> 2, comp = tid & 3;
        const float* q0 = reinterpret_cast<const float*>(&part[0][col]);
        const float* q1 = reinterpret_cast<const float*>(&part[1][col]);
        const float* q2 = reinterpret_cast<const float*>(&part[2][col]);
        const float* q3 = reinterpret_cast<const float*>(&part[3][col]);
        float vsum = (q0[comp] + q1[comp]) + (q2[comp] + q3[comp]);
        atomicAdd(&out[(size_t)b * D + tid], vsum);
    }
}

// ---------------- launcher: simple sequential pipeline ----------------
extern "C" void kernel_launch(void* const* d_in, const int* in_sizes, int n_in,
                              void* d_out, int out_size) {
    const float* logits = (const float*)d_in[0];
    const float* proj = (const float*)d_in[2];
    float* out = (float*)d_out;

    int D = in_sizes[2];                 // 256
    int T = in_sizes[1];                 // 262144
    int B = out_size / D;                // 64
    int N = T / B;                       // 4096
    int K = (int)ceil(0.2 * (double)N);  // 820

    float* dots;
    int* idxList;
    cudaGetSymbolAddress((void**)&dots, g_dot);
    cudaGetSymbolAddress((void**)&idxList, g_idx);

    // 1) per-node dot products (monotone proxy for sigmoid score)
    dot_kernel<<<(T + 31) / 32, 256>>>(logits, proj, dots, 0, T);

    // 2) per-graph exact top-K selection (also zeroes out)
    select_kernel<<<B, 512>>>(dots, idxList, out, N, K, D, 0);

    // 3) gather + segment sum
    gather_sum_kernel<<<B * GSPLIT, 256>>>(logits, idxList, out, K, D, 0);
}